// round 8
// baseline (speedup 1.0000x reference)
#include <cuda_runtime.h>
#include <math.h>

#define B_SZ   128
#define C_SZ   32
#define HW_SZ  144
#define Q_SZ   8
#define O_SZ   10
#define P_SZ   16
#define BDIM   512

#define U_STRIDE 1152

// SMEM layout (floats)
#define U_OFF   0
#define U_SIZE  (32 * U_STRIDE)             // 36864
#define WV_OFF  U_SIZE                       // Wv   [32][10][8] = 2560 (accumulated, log2e-scaled)
#define S_OFF   (WV_OFF + 2560)              // S_s  [32][10][8] = 2560 (iter0: [32][8])
#define SB_OFF  (S_OFF + 2560)               // s_b  [10][16]    = 160
#define PART_OFF (SB_OFF + 160)              // part [2][160]    = 320
#define SMEM_FLOATS (PART_OFF + 320)
#define SMEM_BYTES  (SMEM_FLOATS * 4)

#define LOG2E 1.4426950408889634f

typedef unsigned long long u64p;             // packed f32x2

__device__ __forceinline__ u64p pk2(float lo, float hi) {
    u64p r; asm("mov.b64 %0, {%1, %2};" : "=l"(r) : "f"(lo), "f"(hi)); return r;
}
__device__ __forceinline__ void upk2(u64p v, float& lo, float& hi) {
    asm("mov.b64 {%0, %1}, %2;" : "=f"(lo), "=f"(hi) : "l"(v));
}
__device__ __forceinline__ float ex2f(float x) {
    float y; asm("ex2.approx.ftz.f32 %0, %1;" : "=f"(y) : "f"(x)); return y;
}
#define FMA2(d, a, b, c) asm("fma.rn.f32x2 %0, %1, %2, %3;" : "=l"(d) : "l"(a), "l"(b), "l"(c))
#define MUL2(d, a, b)    asm("mul.rn.f32x2 %0, %1, %2;"      : "=l"(d) : "l"(a), "l"(b))

// ---------------------------------------------------------------------------
// Routing pass for one c. Lanes 0-15: o 0-4, lanes 16-31: o 5-9, 16 spatial
// lanes x 9 steps. Wv slice (log2e-scaled) stays in SMEM and is re-read per
// j-step as BROADCAST LDS.128 (all 16 lanes of a half read the same words —
// conflict-free, ~free). This frees 40 registers vs keeping wv resident, so
// Sp[20] + temporaries fit under the 128-reg cap with no local-memory spills.
// ---------------------------------------------------------------------------
__device__ __forceinline__ void route_c(const float* __restrict__ u_s,
                                        const float* __restrict__ Wv,
                                        float* __restrict__ S_s,
                                        int c, int l16, int half)
{
    const ulonglong2* wvp =
        reinterpret_cast<const ulonglong2*>(Wv + c * 80 + half * 40);

    u64p Sp[20];
#pragma unroll
    for (int z = 0; z < 20; ++z) Sp[z] = 0ULL;

    const ulonglong2* ub =
        reinterpret_cast<const ulonglong2*>(u_s + c * U_STRIDE + l16 * Q_SZ);

    // prefetch j = 0 (one spatial step = 128 floats = 32 ulonglong2)
    ulonglong2 ua = ub[0];
    ulonglong2 uc = ub[1];

#pragma unroll 3
    for (int j = 0; j < 9; ++j) {
        const u64p uq0 = ua.x, uq1 = ua.y, uq2 = uc.x, uq3 = uc.y;
        if (j < 8) {
            ua = ub[(j + 1) * 32];
            uc = ub[(j + 1) * 32 + 1];
        }

        // logits in log2 domain (Wv pre-scaled by log2e); no max needed
        float ex[5];
#pragma unroll
        for (int o = 0; o < 5; ++o) {
            const ulonglong2 w01 = wvp[o * 2];      // broadcast LDS.128
            const ulonglong2 w23 = wvp[o * 2 + 1];  // broadcast LDS.128
            u64p t;
            MUL2(t, uq0, w01.x);
            FMA2(t, uq1, w01.y, t);
            FMA2(t, uq2, w23.x, t);
            FMA2(t, uq3, w23.y, t);
            float lo, hi; upk2(t, lo, hi);
            ex[o] = ex2f(lo + hi);
        }
        const float sa = ((ex[0] + ex[1]) + (ex[2] + ex[3])) + ex[4];
        const float sb = __shfl_xor_sync(0xffffffffu, sa, 16);
        const float r  = __fdividef(1.f, sa + sb);

#pragma unroll
        for (int o = 0; o < 5; ++o) {
            const float ce = ex[o] * r;
            const u64p cep = pk2(ce, ce);
            FMA2(Sp[4*o+0], cep, uq0, Sp[4*o+0]);
            FMA2(Sp[4*o+1], cep, uq1, Sp[4*o+1]);
            FMA2(Sp[4*o+2], cep, uq2, Sp[4*o+2]);
            FMA2(Sp[4*o+3], cep, uq3, Sp[4*o+3]);
        }
    }

    // unpack and split-butterfly reduce 40 values over the 16 spatial lanes
    float v[40];
#pragma unroll
    for (int z = 0; z < 20; ++z) upk2(Sp[z], v[2*z], v[2*z+1]);

    int base = 0;
    {
        const bool up = (l16 & 1);
#pragma unroll
        for (int z = 0; z < 20; ++z) {
            float keep = up ? v[20 + z] : v[z];
            float give = up ? v[z] : v[20 + z];
            v[z] = keep + __shfl_xor_sync(0xffffffffu, give, 1);
        }
        if (up) base += 20;
    }
    {
        const bool up = (l16 & 2);
#pragma unroll
        for (int z = 0; z < 10; ++z) {
            float keep = up ? v[10 + z] : v[z];
            float give = up ? v[z] : v[10 + z];
            v[z] = keep + __shfl_xor_sync(0xffffffffu, give, 2);
        }
        if (up) base += 10;
    }
    {
        const bool up = (l16 & 4);
#pragma unroll
        for (int z = 0; z < 5; ++z) {
            float keep = up ? v[5 + z] : v[z];
            float give = up ? v[z] : v[5 + z];
            v[z] = keep + __shfl_xor_sync(0xffffffffu, give, 4);
        }
        if (up) base += 5;
    }
#pragma unroll
    for (int z = 0; z < 5; ++z)
        v[z] += __shfl_xor_sync(0xffffffffu, v[z], 8);

    if ((l16 & 8) == 0) {
        float* dst = S_s + c * 80 + half * 40 + base;
#pragma unroll
        for (int z = 0; z < 5; ++z) dst[z] = v[z];
    }
}

// partial contract: 320 threads, h = tid/160 handles c in [16h, 16h+16)
template <bool PER_O>
__device__ __forceinline__ void contract_partial(const float* __restrict__ Wg,
                                                 const float* __restrict__ S_s,
                                                 float* __restrict__ part, int tid)
{
    if (tid < 320) {
        const int h   = (tid >= 160);
        const int idx = tid - h * 160;
        const int o = idx >> 4, p = idx & 15;
        float a0 = 0.f, a1 = 0.f, a2 = 0.f, a3 = 0.f;
        const int c0 = h * 16;
#pragma unroll
        for (int k = 0; k < 16; ++k) {
            const int cc = c0 + k;
            const float4* wp =
                reinterpret_cast<const float4*>(Wg + cc * 1280 + o * 128 + p * 8);
            const float4* sp = reinterpret_cast<const float4*>(
                S_s + (PER_O ? (cc * 80 + o * 8) : (cc * 8)));
            float4 w0 = wp[0], w1 = wp[1], b0 = sp[0], b1 = sp[1];
            a0 += w0.x * b0.x + w0.y * b0.y;
            a1 += w0.z * b0.z + w0.w * b0.w;
            a2 += w1.x * b1.x + w1.y * b1.y;
            a3 += w1.z * b1.z + w1.w * b1.w;
        }
        part[h * 160 + idx] = (a0 + a1) + (a2 + a3);
    }
}

// Wv[c][o][q] (+)= log2e * sum_p W[c,o,p,q] * squash(s)[o][p]  (threads 0..319)
template <bool ACC>
__device__ __forceinline__ void compute_Wv(const float* __restrict__ Wg,
                                           const float* __restrict__ s_b,
                                           float* __restrict__ Wv, int tid)
{
    if (tid < 320) {
        const int cc = tid / 10;
        const int o  = tid - cc * 10;
        const float* srow = s_b + o * 16;
        float sv[16];
        float sn = 0.f;
#pragma unroll
        for (int p = 0; p < 16; ++p) { sv[p] = srow[p]; sn += sv[p] * sv[p]; }
        const float sc = __fdividef(__fsqrt_rn(sn) * LOG2E, 1.f + sn);

        const float* wrow = Wg + cc * 1280 + o * 128;
        float acc[8];
#pragma unroll
        for (int q = 0; q < 8; ++q) acc[q] = 0.f;
#pragma unroll
        for (int p = 0; p < 16; ++p) {
            const float vp = sv[p] * sc;
            const float4* wp = reinterpret_cast<const float4*>(wrow + p * 8);
            float4 w0 = wp[0], w1 = wp[1];
            acc[0] += w0.x * vp; acc[1] += w0.y * vp;
            acc[2] += w0.z * vp; acc[3] += w0.w * vp;
            acc[4] += w1.x * vp; acc[5] += w1.y * vp;
            acc[6] += w1.z * vp; acc[7] += w1.w * vp;
        }
        float4* dst = reinterpret_cast<float4*>(Wv + cc * 80 + o * 8);
        if (ACC) {
            float4 o0 = dst[0], o1 = dst[1];
            dst[0] = make_float4(o0.x + acc[0], o0.y + acc[1], o0.z + acc[2], o0.w + acc[3]);
            dst[1] = make_float4(o1.x + acc[4], o1.y + acc[5], o1.z + acc[6], o1.w + acc[7]);
        } else {
            dst[0] = make_float4(acc[0], acc[1], acc[2], acc[3]);
            dst[1] = make_float4(acc[4], acc[5], acc[6], acc[7]);
        }
    }
}

__global__ __launch_bounds__(BDIM, 1)
void caps_routing_kernel(const float* __restrict__ xg,
                         const float* __restrict__ Wg,
                         float* __restrict__ outg)
{
    extern __shared__ float sm[];
    float* u_s  = sm + U_OFF;
    float* Wv   = sm + WV_OFF;
    float* S_s  = sm + S_OFF;
    float* s_b  = sm + SB_OFF;
    float* part = sm + PART_OFF;

    const int b    = blockIdx.x;
    const int tid  = threadIdx.x;
    const int w    = tid >> 5;
    const int lane = tid & 31;
    const int l16  = lane & 15;
    const int half = lane >> 4;

    // ---- fused load + iteration 0 partial sums
#pragma unroll
    for (int ci = 0; ci < 2; ++ci) {
        const int c = w + 16 * ci;
        const float4* src =
            reinterpret_cast<const float4*>(xg + (size_t)b * 36864 + c * 1152);
        float4* dst = reinterpret_cast<float4*>(u_s + c * U_STRIDE);
        float4 acc = make_float4(0.f, 0.f, 0.f, 0.f);
#pragma unroll
        for (int k = 0; k < 9; ++k) {
            float4 t = src[lane + 32 * k];
            dst[lane + 32 * k] = t;
            acc.x += t.x; acc.y += t.y; acc.z += t.z; acc.w += t.w;
        }
#pragma unroll
        for (int msk = 2; msk <= 16; msk <<= 1) {
            acc.x += __shfl_xor_sync(0xffffffffu, acc.x, msk);
            acc.y += __shfl_xor_sync(0xffffffffu, acc.y, msk);
            acc.z += __shfl_xor_sync(0xffffffffu, acc.z, msk);
            acc.w += __shfl_xor_sync(0xffffffffu, acc.w, msk);
        }
        if (lane < 2) {
            float4* so = reinterpret_cast<float4*>(S_s + c * 8 + lane * 4);
            so[0] = make_float4(acc.x * 0.1f, acc.y * 0.1f, acc.z * 0.1f, acc.w * 0.1f);
        }
    }
    __syncthreads();

    // ---- iteration 0 contract + Wv(v0)
    contract_partial<false>(Wg, S_s, part, tid);
    __syncthreads();
    if (tid < 160) s_b[tid] = part[tid] + part[160 + tid];
    __syncthreads();
    compute_Wv<false>(Wg, s_b, Wv, tid);
    __syncthreads();

    // ---- iteration 1
    route_c(u_s, Wv, S_s, w, l16, half);
    route_c(u_s, Wv, S_s, w + 16, l16, half);
    __syncthreads();
    contract_partial<true>(Wg, S_s, part, tid);
    __syncthreads();
    if (tid < 160) s_b[tid] = part[tid] + part[160 + tid];
    __syncthreads();
    compute_Wv<true>(Wg, s_b, Wv, tid);
    __syncthreads();

    // ---- iteration 2
    route_c(u_s, Wv, S_s, w, l16, half);
    route_c(u_s, Wv, S_s, w + 16, l16, half);
    __syncthreads();
    contract_partial<true>(Wg, S_s, part, tid);
    __syncthreads();
    if (tid < 160) s_b[tid] = part[tid] + part[160 + tid];
    __syncthreads();

    // out = squash(s2)
    if (tid < 160) {
        const int o = tid >> 4;
        const float* srow = s_b + o * 16;
        float sn = 0.f;
#pragma unroll
        for (int p = 0; p < 16; ++p) { float t = srow[p]; sn += t * t; }
        const float sc = __fdividef(__fsqrt_rn(sn), 1.f + sn);
        outg[b * 160 + tid] = s_b[tid] * sc;
    }
}

extern "C" void kernel_launch(void* const* d_in, const int* in_sizes, int n_in,
                              void* d_out, int out_size)
{
    const float* x = (const float*)d_in[0];
    const float* W = (const float*)d_in[1];
    if (n_in >= 2 && in_sizes[0] < in_sizes[1]) {
        const float* t = x; x = W; W = t;
    }
    (void)out_size;

    cudaFuncSetAttribute(caps_routing_kernel,
                         cudaFuncAttributeMaxDynamicSharedMemorySize, SMEM_BYTES);
    caps_routing_kernel<<<B_SZ, BDIM, SMEM_BYTES>>>(x, W, (float*)d_out);
}

// round 9
// speedup vs baseline: 1.2051x; 1.2051x over previous
#include <cuda_runtime.h>
#include <math.h>

#define B_SZ   128
#define Q_SZ   8
#define BDIM   512

#define U_STRIDE 1152

// SMEM layout (floats)
#define U_OFF   0
#define U_SIZE  (32 * U_STRIDE)             // 36864
#define WV_OFF  U_SIZE                       // Wv  [32][10][8] = 2560 (accumulated, log2e-scaled)
#define S_OFF   (WV_OFF + 2560)              // S_s [32][10][8] = 2560 (iter0: [32][8])
#define SB_OFF  (S_OFF + 2560)               // s_b [10][16] = 160 (final squashed v)
#define VB_OFF  (SB_OFF + 160)               // v_b [10][16] = 160 (log2e-scaled v)
#define SMEM_FLOATS (VB_OFF + 160)
#define SMEM_BYTES  (SMEM_FLOATS * 4)

#define LOG2E 1.4426950408889634f

typedef unsigned long long u64p;             // packed f32x2

__device__ __forceinline__ u64p pk2(float lo, float hi) {
    u64p r; asm("mov.b64 %0, {%1, %2};" : "=l"(r) : "f"(lo), "f"(hi)); return r;
}
__device__ __forceinline__ void upk2(u64p v, float& lo, float& hi) {
    asm("mov.b64 {%0, %1}, %2;" : "=f"(lo), "=f"(hi) : "l"(v));
}
__device__ __forceinline__ float ex2f(float x) {
    float y; asm("ex2.approx.ftz.f32 %0, %1;" : "=f"(y) : "f"(x)); return y;
}
#define FMA2(d, a, b, c) asm("fma.rn.f32x2 %0, %1, %2, %3;" : "=l"(d) : "l"(a), "l"(b), "l"(c))
#define MUL2(d, a, b)    asm("mul.rn.f32x2 %0, %1, %2;"      : "=l"(d) : "l"(a), "l"(b))

// ---------------------------------------------------------------------------
// Routing pass for one c (unchanged from best variant): lanes 0-15 o 0-4,
// lanes 16-31 o 5-9; wv from SMEM as broadcast LDS; no-max log2 softmax.
// ---------------------------------------------------------------------------
__device__ __forceinline__ void route_c(const float* __restrict__ u_s,
                                        const float* __restrict__ Wv,
                                        float* __restrict__ S_s,
                                        int c, int l16, int half)
{
    const ulonglong2* wvp =
        reinterpret_cast<const ulonglong2*>(Wv + c * 80 + half * 40);

    u64p Sp[20];
#pragma unroll
    for (int z = 0; z < 20; ++z) Sp[z] = 0ULL;

    const ulonglong2* ub =
        reinterpret_cast<const ulonglong2*>(u_s + c * U_STRIDE + l16 * Q_SZ);

    ulonglong2 ua = ub[0];
    ulonglong2 uc = ub[1];

#pragma unroll 2
    for (int j = 0; j < 9; ++j) {
        const u64p uq0 = ua.x, uq1 = ua.y, uq2 = uc.x, uq3 = uc.y;
        if (j < 8) {
            ua = ub[(j + 1) * 32];
            uc = ub[(j + 1) * 32 + 1];
        }

        float ex[5];
#pragma unroll
        for (int o = 0; o < 5; ++o) {
            const ulonglong2 w01 = wvp[o * 2];
            const ulonglong2 w23 = wvp[o * 2 + 1];
            u64p t;
            MUL2(t, uq0, w01.x);
            FMA2(t, uq1, w01.y, t);
            FMA2(t, uq2, w23.x, t);
            FMA2(t, uq3, w23.y, t);
            float lo, hi; upk2(t, lo, hi);
            ex[o] = ex2f(lo + hi);
        }
        const float sa = ((ex[0] + ex[1]) + (ex[2] + ex[3])) + ex[4];
        const float sb = __shfl_xor_sync(0xffffffffu, sa, 16);
        const float r  = __fdividef(1.f, sa + sb);

#pragma unroll
        for (int o = 0; o < 5; ++o) {
            const float ce = ex[o] * r;
            const u64p cep = pk2(ce, ce);
            FMA2(Sp[4*o+0], cep, uq0, Sp[4*o+0]);
            FMA2(Sp[4*o+1], cep, uq1, Sp[4*o+1]);
            FMA2(Sp[4*o+2], cep, uq2, Sp[4*o+2]);
            FMA2(Sp[4*o+3], cep, uq3, Sp[4*o+3]);
        }
    }

    float v[40];
#pragma unroll
    for (int z = 0; z < 20; ++z) upk2(Sp[z], v[2*z], v[2*z+1]);

    int base = 0;
    {
        const bool up = (l16 & 1);
#pragma unroll
        for (int z = 0; z < 20; ++z) {
            float keep = up ? v[20 + z] : v[z];
            float give = up ? v[z] : v[20 + z];
            v[z] = keep + __shfl_xor_sync(0xffffffffu, give, 1);
        }
        if (up) base += 20;
    }
    {
        const bool up = (l16 & 2);
#pragma unroll
        for (int z = 0; z < 10; ++z) {
            float keep = up ? v[10 + z] : v[z];
            float give = up ? v[z] : v[10 + z];
            v[z] = keep + __shfl_xor_sync(0xffffffffu, give, 2);
        }
        if (up) base += 10;
    }
    {
        const bool up = (l16 & 4);
#pragma unroll
        for (int z = 0; z < 5; ++z) {
            float keep = up ? v[5 + z] : v[z];
            float give = up ? v[z] : v[5 + z];
            v[z] = keep + __shfl_xor_sync(0xffffffffu, give, 4);
        }
        if (up) base += 5;
    }
#pragma unroll
    for (int z = 0; z < 5; ++z)
        v[z] += __shfl_xor_sync(0xffffffffu, v[z], 8);

    if ((l16 & 8) == 0) {
        float* dst = S_s + c * 80 + half * 40 + base;
#pragma unroll
        for (int z = 0; z < 5; ++z) dst[z] = v[z];
    }
}

// ---------------------------------------------------------------------------
// Fused contract + squash + v_b, warp-cooperative. Warp w < 10 owns o = w.
// Lane (p = lane&15, h = lane>>4) sums over all 32 c and its q-half:
// one warp-LDG.128 covers one c's full [16p][8q] slab (512B, 4 wavefronts).
// q-half combine, squash norm, and v computation all via shuffles -> ONE phase.
// LAST: write squashed v into s_b (final output); else v_b = v * scale * LOG2E.
// ---------------------------------------------------------------------------
template <bool PER_O, bool LAST>
__device__ __forceinline__ void contract_v(const float* __restrict__ Wg,
                                           const float* __restrict__ S_s,
                                           float* __restrict__ s_b,
                                           float* __restrict__ v_b,
                                           int w, int lane)
{
    if (w < 10) {
        const int o = w;
        const int p = lane & 15;
        const int h = lane >> 4;
        const float* wbase = Wg + o * 128 + p * 8 + h * 4;
        float a0 = 0.f, a1 = 0.f, a2 = 0.f, a3 = 0.f;
#pragma unroll 8
        for (int c = 0; c < 32; ++c) {
            const float4 w4 = *reinterpret_cast<const float4*>(wbase + c * 1280);
            const float4 s4 = *reinterpret_cast<const float4*>(
                S_s + (PER_O ? (c * 80 + o * 8 + h * 4) : (c * 8 + h * 4)));
            a0 += w4.x * s4.x; a1 += w4.y * s4.y;
            a2 += w4.z * s4.z; a3 += w4.w * s4.w;
        }
        float s = (a0 + a1) + (a2 + a3);
        s += __shfl_xor_sync(0xffffffffu, s, 16);     // combine q-halves

        float sq = s * s;
        sq += __shfl_xor_sync(0xffffffffu, sq, 1);
        sq += __shfl_xor_sync(0xffffffffu, sq, 2);
        sq += __shfl_xor_sync(0xffffffffu, sq, 4);
        sq += __shfl_xor_sync(0xffffffffu, sq, 8);    // ||s||^2 over 16 p-lanes

        if (LAST) {
            const float sc = __fdividef(__fsqrt_rn(sq), 1.f + sq);
            if (h == 0) s_b[o * 16 + p] = s * sc;
        } else {
            const float sc = __fdividef(__fsqrt_rn(sq) * LOG2E, 1.f + sq);
            if (h == 0) v_b[o * 16 + p] = s * sc;
        }
    }
}

// ---------------------------------------------------------------------------
// Warp-cooperative Wv: all 16 warps, 20 (c,o) pairs each. Lane (pg=lane>>3,
// q=lane&7). Load wrow[i*32+lane] -> warp reads 128 CONSECUTIVE floats per
// instruction (1 wavefront, vs 32 in the old per-thread layout). p = pg+4i.
// Reduce over pg with 2 shuffles; lanes 0-7 hold Wv[c][o][q].
// ---------------------------------------------------------------------------
template <bool ACC>
__device__ __forceinline__ void compute_Wv_coop(const float* __restrict__ Wg,
                                                const float* __restrict__ v_b,
                                                float* __restrict__ Wv,
                                                int w, int lane)
{
    const int q  = lane & 7;
    const int pg = lane >> 3;
#pragma unroll 5
    for (int m = 0; m < 20; ++m) {
        const int pair = w * 20 + m;          // 0..319
        const int c = pair / 10;
        const int o = pair - c * 10;
        const float* wrow = Wg + c * 1280 + o * 128;
        const float* vrow = v_b + o * 16 + pg;
        float acc = wrow[lane]       * vrow[0]
                  + wrow[32 + lane]  * vrow[4]
                  + wrow[64 + lane]  * vrow[8]
                  + wrow[96 + lane]  * vrow[12];
        acc += __shfl_xor_sync(0xffffffffu, acc, 8);
        acc += __shfl_xor_sync(0xffffffffu, acc, 16);
        if (lane < 8) {
            float* dst = Wv + c * 80 + o * 8 + q;
            *dst = ACC ? (*dst + acc) : acc;
        }
    }
}

__global__ __launch_bounds__(BDIM, 1)
void caps_routing_kernel(const float* __restrict__ xg,
                         const float* __restrict__ Wg,
                         float* __restrict__ outg)
{
    extern __shared__ float sm[];
    float* u_s = sm + U_OFF;
    float* Wv  = sm + WV_OFF;
    float* S_s = sm + S_OFF;
    float* s_b = sm + SB_OFF;
    float* v_b = sm + VB_OFF;

    const int b    = blockIdx.x;
    const int tid  = threadIdx.x;
    const int w    = tid >> 5;
    const int lane = tid & 31;
    const int l16  = lane & 15;
    const int half = lane >> 4;

    // ---- fused load + iteration 0 partial sums (c_ij = 1/10) ----
#pragma unroll
    for (int ci = 0; ci < 2; ++ci) {
        const int c = w + 16 * ci;
        const float4* src =
            reinterpret_cast<const float4*>(xg + (size_t)b * 36864 + c * 1152);
        float4* dst = reinterpret_cast<float4*>(u_s + c * U_STRIDE);
        float4 acc = make_float4(0.f, 0.f, 0.f, 0.f);
#pragma unroll
        for (int k = 0; k < 9; ++k) {
            float4 t = src[lane + 32 * k];
            dst[lane + 32 * k] = t;
            acc.x += t.x; acc.y += t.y; acc.z += t.z; acc.w += t.w;
        }
#pragma unroll
        for (int msk = 2; msk <= 16; msk <<= 1) {
            acc.x += __shfl_xor_sync(0xffffffffu, acc.x, msk);
            acc.y += __shfl_xor_sync(0xffffffffu, acc.y, msk);
            acc.z += __shfl_xor_sync(0xffffffffu, acc.z, msk);
            acc.w += __shfl_xor_sync(0xffffffffu, acc.w, msk);
        }
        if (lane < 2) {    // lane0 -> q0-3, lane1 -> q4-7
            float4* so = reinterpret_cast<float4*>(S_s + c * 8 + lane * 4);
            so[0] = make_float4(acc.x * 0.1f, acc.y * 0.1f, acc.z * 0.1f, acc.w * 0.1f);
        }
    }
    __syncthreads();

    // ---- iteration 0: contract + squash + v_b, then Wv(v0)
    contract_v<false, false>(Wg, S_s, s_b, v_b, w, lane);
    __syncthreads();
    compute_Wv_coop<false>(Wg, v_b, Wv, w, lane);
    __syncthreads();

    // ---- iteration 1
    route_c(u_s, Wv, S_s, w, l16, half);
    route_c(u_s, Wv, S_s, w + 16, l16, half);
    __syncthreads();
    contract_v<true, false>(Wg, S_s, s_b, v_b, w, lane);
    __syncthreads();
    compute_Wv_coop<true>(Wg, v_b, Wv, w, lane);
    __syncthreads();

    // ---- iteration 2
    route_c(u_s, Wv, S_s, w, l16, half);
    route_c(u_s, Wv, S_s, w + 16, l16, half);
    __syncthreads();
    contract_v<true, true>(Wg, S_s, s_b, v_b, w, lane);   // writes squashed v -> s_b
    __syncthreads();

    if (tid < 160) outg[b * 160 + tid] = s_b[tid];
}

extern "C" void kernel_launch(void* const* d_in, const int* in_sizes, int n_in,
                              void* d_out, int out_size)
{
    const float* x = (const float*)d_in[0];
    const float* W = (const float*)d_in[1];
    if (n_in >= 2 && in_sizes[0] < in_sizes[1]) {
        const float* t = x; x = W; W = t;
    }
    (void)out_size;

    cudaFuncSetAttribute(caps_routing_kernel,
                         cudaFuncAttributeMaxDynamicSharedMemorySize, SMEM_BYTES);
    caps_routing_kernel<<<B_SZ, BDIM, SMEM_BYTES>>>(x, W, (float*)d_out);
}